// round 17
// baseline (speedup 1.0000x reference)
#include <cuda_runtime.h>
#include <cuda_bf16.h>

#define OUT_SZ 7
#define NCELL (OUT_SZ * OUT_SZ)      // 49
#define NCH 256
#define NQ (NCH / 4)                 // 64 float4 per channel row
#define F4_PER_ROI (NCELL * NQ)      // 3136; 3136 % 32 == 0
#define CHUNKS_PER_ROI (F4_PER_ROI / 32)   // 98 warp-chunks per ROI
#define NTHREADS 256
#define NBLOCKS 1184                 // 148 SMs x 8 CTAs
#define TOTAL_WARPS (NBLOCKS * NTHREADS / 32)  // 9472

// level thresholds on wh = roi_h*roi_w:
//   level >= c  <=>  wh >= 224^2 * 2^(2*(c-4)),  c = 2.5, 3.5, 4.5
#define T3 6272.0f      // 224^2 / 8
#define T4 25088.0f     // 224^2 / 2
#define T5 100352.0f    // 224^2 * 2

__global__ __launch_bounds__(NTHREADS, 8)
void roialign_kernel(const float* __restrict__ p2,
                     const float* __restrict__ p3,
                     const float* __restrict__ p4,
                     const float* __restrict__ p5,
                     const float* __restrict__ rois,
                     float* __restrict__ out,
                     int total_chunks)
{
    int tid  = threadIdx.x;
    int lane = tid & 31;
    int gw   = (blockIdx.x * NTHREADS + tid) >> 5;   // global warp id

    float4* o4 = (float4*)out;
    float4 zero = make_float4(0.f, 0.f, 0.f, 0.f);

    for (int ch = gw; ch < total_chunks; ch += TOTAL_WARPS) {
        int roi = ch / CHUNKS_PER_ROI;               // warp-uniform
        int co  = ch - roi * CHUNKS_PER_ROI;         // chunk within ROI, 0..97
        int o   = (co << 5) + lane;                  // f4 index within ROI

        // ---- warp-uniform ROI decode (values identical across lanes) ----
        const float* r = rois + (size_t)roi * 5;     // [batch, x1, y1, x2, y2]
        float rx1 = __ldg(r + 1), ry1 = __ldg(r + 2);
        float rx2 = __ldg(r + 3), ry2 = __ldg(r + 4);

        float dx = rx2 - rx1;
        float dy = ry2 - ry1;
        float wh = dy * dx;
        int level = 2 + (wh >= T3) + (wh >= T4) + (wh >= T5);

        // c = (H-1) * 2^-level
        float c = level < 4 ? (level == 2 ? 63.75f  : 15.875f)
                            : (level == 4 ? 3.9375f : 0.96875f);
        float Hm1 = (float)((1024 >> level) - 1);

        // crop y-axis uses rx, x-axis uses ry (coordinate-swap quirk).
        float y_base = rx1 * c;
        float x_base = ry1 * c;

        // Cell (0,0) is the coordinate minimum; if invalid, whole ROI is zero.
        if ((y_base > Hm1) | (x_base > Hm1)) {       // warp-uniform branch
            o4[(size_t)roi * F4_PER_ROI + o] = zero;
            continue;
        }

        // ---- rare valid-ROI path ----
        const float* fm = level < 4 ? (level == 2 ? p2 : p3)
                                    : (level == 4 ? p4 : p5);
        int b = (int)__ldg(r + 0);
        float c6 = c * (1.0f / 6.0f);
        int   Hm1i = (1024 >> level) - 1;
        int   rowstride = 65536 >> level;            // H * NQ (float4 units)
        float h_scale = dx * c6;
        float w_scale = dy * c6;

        int cell = o >> 6;                           // warp-uniform? no: o has lane
        int cq   = o & (NQ - 1);
        int i    = cell / OUT_SZ;
        int j    = cell - i * OUT_SZ;

        float in_y = fmaf((float)i, h_scale, y_base);
        float in_x = fmaf((float)j, w_scale, x_base);
        bool valid = (in_y >= 0.0f) & (in_y <= Hm1) &
                     (in_x >= 0.0f) & (in_x <= Hm1);

        float4 v = zero;
        if (valid) {
            const float4* fm_b = (const float4*)(fm + ((size_t)b << (28 - 2 * level)));
            float fy = floorf(in_y);
            float fx = floorf(in_x);
            float ly = in_y - fy;
            float lx = in_x - fx;
            int y0 = (int)fy;                        // valid => in [0, Hm1i]
            int x0 = (int)fx;
            int yc = (int)fminf(ceilf(in_y), Hm1);
            int xc = (int)fminf(ceilf(in_x), Hm1);
            (void)Hm1i;

            const float4* r0 = fm_b + y0 * rowstride;
            const float4* r1 = fm_b + yc * rowstride;
            float4 tl = __ldg(r0 + x0 * NQ + cq);
            float4 tr = __ldg(r0 + xc * NQ + cq);
            float4 bl = __ldg(r1 + x0 * NQ + cq);
            float4 br = __ldg(r1 + xc * NQ + cq);

            float4 top, bot;
            top.x = fmaf(tr.x - tl.x, lx, tl.x);
            top.y = fmaf(tr.y - tl.y, lx, tl.y);
            top.z = fmaf(tr.z - tl.z, lx, tl.z);
            top.w = fmaf(tr.w - tl.w, lx, tl.w);
            bot.x = fmaf(br.x - bl.x, lx, bl.x);
            bot.y = fmaf(br.y - bl.y, lx, bl.y);
            bot.z = fmaf(br.z - bl.z, lx, bl.z);
            bot.w = fmaf(br.w - bl.w, lx, bl.w);
            v.x = fmaf(bot.x - top.x, ly, top.x);
            v.y = fmaf(bot.y - top.y, ly, top.y);
            v.z = fmaf(bot.z - top.z, ly, top.z);
            v.w = fmaf(bot.w - top.w, ly, top.w);
        }
        o4[(size_t)roi * F4_PER_ROI + o] = v;
    }
}

extern "C" void kernel_launch(void* const* d_in, const int* in_sizes, int n_in,
                              void* d_out, int out_size)
{
    const float* p2   = (const float*)d_in[0];
    const float* p3   = (const float*)d_in[1];
    const float* p4   = (const float*)d_in[2];
    const float* p5   = (const float*)d_in[3];
    const float* rois = (const float*)d_in[4];
    float* out = (float*)d_out;
    int n_rois = in_sizes[4] / 5;
    int total_chunks = n_rois * CHUNKS_PER_ROI;

    roialign_kernel<<<NBLOCKS, NTHREADS>>>(p2, p3, p4, p5, rois, out, total_chunks);
}